// round 14
// baseline (speedup 1.0000x reference)
#include <cuda_runtime.h>
#include <math.h>

#define B_    256
#define C_    128
#define D_    128
#define N_    100000
#define NID_  131072
#define K_    100
#define C2_   256
#define M_    (B_*K_)

// ------------------------- scratch (device globals) -------------------------
__device__ float g_lhs_proj[B_*D_];
__device__ float g_emb_off[B_];
__device__ float g_idg_off[B_];
__device__ float g_idgnn[NID_];
__device__ int   g_pos[B_*N_];          // 25.6M ints
__device__ int   g_topk[M_];
__device__ float g_x [M_*C2_];
__device__ float g_q [M_*C2_];
__device__ float g_k [M_*C2_];
__device__ float g_v [M_*C2_];
__device__ float g_o [M_*C2_];
__device__ float g_op[M_*C2_];
__device__ float g_h [M_*C2_];
__device__ float g_f [M_*C2_];
__device__ float g_x2[M_*C2_];
__device__ float g_tr[M_*D_];

// ------------------------- 0) init pos table -------------------------
__global__ void k_initpos() {
    int i = blockIdx.x * blockDim.x + threadIdx.x;   // 25000 x 1024 = 25.6M exact
    g_pos[i] = -1;
}

// ------------------------- 1) lhs_proj + offsets (strict sequential) -------------------------
__global__ void k_lhsproj(const float* __restrict__ lhs, const float* __restrict__ wp,
                          const float* __restrict__ bp, const float* __restrict__ woe,
                          const float* __restrict__ boe, const float* __restrict__ woi,
                          const float* __restrict__ boi) {
    __shared__ float s_l[C_];
    __shared__ float sacc[C_];
    int b = blockIdx.x, t = threadIdx.x;     // 128 threads
    s_l[t] = lhs[b*C_ + t];
    __syncthreads();
    float acc = 0.f;
    for (int c = 0; c < C_; c++) acc = __fmaf_rn(s_l[c], wp[c*D_ + t], acc);
    acc = __fadd_rn(acc, bp[t]);
    g_lhs_proj[b*D_ + t] = acc;
    sacc[t] = acc;
    __syncthreads();
    if (t == 0) {
        float eo = 0.f;
        for (int c = 0; c < C_; c++) eo = __fmaf_rn(sacc[c], woe[c], eo);
        g_emb_off[b] = __fadd_rn(eo, boe[0]);
        float io = 0.f;
        for (int c = 0; c < C_; c++) io = __fmaf_rn(sacc[c], woi[c], io);
        g_idg_off[b] = __fadd_rn(io, boi[0]);
    }
}

// ------------------------- 2) idgnn logits + pos winners -------------------------
__global__ __launch_bounds__(128) void k_idgnn(const float* __restrict__ gnn,
                        const float* __restrict__ lhs,
                        const int* __restrict__ bidx, const int* __restrict__ ridx,
                        const float* __restrict__ wh, const float* __restrict__ bh) {
    __shared__ float sW[C_];
    __shared__ float sG[4][C_];
    __shared__ float sL[4][C_];
    int t = threadIdx.x, w = t >> 5, lane = t & 31;
    sW[t] = wh[t];
    int node = blockIdx.x * 4 + w;
    if (node >= NID_) return;
    int bt = bidx[node];
    for (int c = lane; c < C_; c += 32) {
        sG[w][c] = gnn[(size_t)node*C_ + c];
        sL[w][c] = lhs[(size_t)bt*C_ + c];
    }
    __syncthreads();
    if (lane == 0) {
        float sh = 0.f;
        for (int c = 0; c < C_; c++) sh = __fmaf_rn(sG[w][c], sW[c], sh);
        float sl = 0.f;
        for (int c = 0; c < C_; c++) {
            float p = __fmul_rn(sL[w][c], sG[w][c]);
            sl = __fadd_rn(sl, p);
        }
        float v = __fadd_rn(__fadd_rn(__fadd_rn(sh, bh[0]), sl), g_idg_off[bt]);
        g_idgnn[node] = v;
        atomicMax(&g_pos[(size_t)bt*N_ + ridx[node]], node);   // last-update-wins
    }
}

// ------------------------- 3) embgnn GEMM (sequential-k fma, validated) -------------------------
__global__ __launch_bounds__(256) void k_embgnn(const float* __restrict__ E,
                                                float* __restrict__ out) {
    __shared__ float As[32][132];
    __shared__ float Es[32][68];
    int tid = threadIdx.x;
    int tx = tid & 15, ty = tid >> 4;
    int n0 = blockIdx.x * 64, m0 = blockIdx.y * 128;
    float acc[8][4] = {};
    for (int kc = 0; kc < D_; kc += 32) {
        #pragma unroll
        for (int v = 0; v < 4; v++) {
            int q = tid + v*256;
            int am = q >> 3, ak = q & 7;
            float4 t4 = *(const float4*)(g_lhs_proj + (size_t)(m0+am)*D_ + kc + ak*4);
            As[ak*4+0][am] = t4.x; As[ak*4+1][am] = t4.y;
            As[ak*4+2][am] = t4.z; As[ak*4+3][am] = t4.w;
        }
        #pragma unroll
        for (int v = 0; v < 2; v++) {
            int q = tid + v*256;
            int en = q >> 3, ek = q & 7;
            int n = n0 + en;
            float4 t4 = make_float4(0.f,0.f,0.f,0.f);
            if (n < N_) t4 = *(const float4*)(E + (size_t)n*D_ + kc + ek*4);
            Es[ek*4+0][en] = t4.x; Es[ek*4+1][en] = t4.y;
            Es[ek*4+2][en] = t4.z; Es[ek*4+3][en] = t4.w;
        }
        __syncthreads();
        #pragma unroll
        for (int k = 0; k < 32; k++) {
            float4 a0 = *(const float4*)&As[k][ty*8];
            float4 a1 = *(const float4*)&As[k][ty*8+4];
            float4 w0 = *(const float4*)&Es[k][tx*4];
            float av[8] = {a0.x,a0.y,a0.z,a0.w,a1.x,a1.y,a1.z,a1.w};
            #pragma unroll
            for (int i = 0; i < 8; i++) {
                acc[i][0] = __fmaf_rn(av[i], w0.x, acc[i][0]);
                acc[i][1] = __fmaf_rn(av[i], w0.y, acc[i][1]);
                acc[i][2] = __fmaf_rn(av[i], w0.z, acc[i][2]);
                acc[i][3] = __fmaf_rn(av[i], w0.w, acc[i][3]);
            }
        }
        __syncthreads();
    }
    #pragma unroll
    for (int i = 0; i < 8; i++) {
        int m = m0 + ty*8 + i;
        float off = g_emb_off[m];
        #pragma unroll
        for (int j = 0; j < 4; j++) {
            int n = n0 + tx*4 + j;
            if (n < N_) out[(size_t)m*N_ + n] = __fadd_rn(acc[i][j], off);
        }
    }
}

// ------------------------- 4) scatter winners -------------------------
__global__ void k_scatter(const int* __restrict__ bidx, const int* __restrict__ ridx,
                          float* __restrict__ out) {
    int i = blockIdx.x * blockDim.x + threadIdx.x;
    if (i >= NID_) return;
    size_t slot = (size_t)bidx[i]*N_ + ridx[i];
    if (g_pos[slot] == i) out[slot] = g_idgnn[i];
}

// ------------------------- 5) top-K: EXACT std::partial_sort emulation -------------------------
// Emulates libstdc++ partial_sort(idx, idx+K, idx+N, cmp) with cmp(a,b) = key[a] > key[b]
// (value-only comparator, no index tie-break), as used by XLA-CPU's TopK custom call.
// Any strictly monotone key gives identical comparator outcomes; ties (equal float bits)
// are ordered by the exact gcc heap mechanics below.
__device__ __forceinline__ unsigned fkey(float x) {
    unsigned u = __float_as_uint(x);
    return (u & 0x80000000u) ? ~u : (u | 0x80000000u);
}

// gcc __adjust_heap: sift hole to bottom choosing cmp-greater child, even-length
// last-child special case, then __push_heap the value back up.
__device__ void heap_adjust(int* hI, unsigned* hK, int hole, int len,
                            int vI, unsigned vK) {
    int top = hole;
    int sc = hole;
    while (sc < (len - 1) / 2) {
        sc = 2 * (sc + 1);
        if (hK[sc] > hK[sc - 1]) sc--;          // pick cmp-greater child (smaller key)
        hI[hole] = hI[sc]; hK[hole] = hK[sc];
        hole = sc;
    }
    if ((len & 1) == 0 && sc == (len - 2) / 2) {
        sc = 2 * (sc + 1);
        hI[hole] = hI[sc - 1]; hK[hole] = hK[sc - 1];
        hole = sc - 1;
    }
    while (hole > top) {                         // __push_heap
        int par = (hole - 1) >> 1;
        if (hK[par] > vK) { hI[hole] = hI[par]; hK[hole] = hK[par]; hole = par; }
        else break;
    }
    hI[hole] = vI; hK[hole] = vK;
}

__global__ __launch_bounds__(256) void k_topk(const float* __restrict__ logits,
                                              float* __restrict__ out) {
    __shared__ int      sI[8][K_];
    __shared__ unsigned sK[8][K_];
    int w = threadIdx.x >> 5, lane = threadIdx.x & 31;
    int r = blockIdx.x * 8 + w;
    const float* row = logits + (size_t)r * N_;
    int* hI = sI[w]; unsigned* hK = sK[w];

    // iota + keys for first K
    for (int i = lane; i < K_; i += 32) { hI[i] = i; hK[i] = fkey(row[i]); }
    __syncwarp();
    // __make_heap (heap top = cmp-max = smallest key = current 100th value)
    if (lane == 0)
        for (int p = (K_ - 2) / 2; p >= 0; p--)
            heap_adjust(hI, hK, p, K_, hI[p], hK[p]);
    __syncwarp();
    unsigned kmin = hK[0];

    // stream i = K..N-1 in order; insert iff key > heap-top key (strict)
    for (int base = K_; base < N_; base += 256) {
        unsigned kk[8];
        #pragma unroll
        for (int j = 0; j < 8; j++) {
            int i = base + j*32 + lane;
            kk[j] = (i < N_) ? fkey(row[i]) : 0u;
        }
        #pragma unroll
        for (int j = 0; j < 8; j++) {
            int ib = base + j*32;
            if (ib >= N_) break;
            unsigned m = __ballot_sync(0xffffffffu, (ib + lane) < N_ && kk[j] > kmin);
            while (m) {
                int l = __ffs(m) - 1; m &= m - 1;
                unsigned kv = __shfl_sync(0xffffffffu, kk[j], l);
                if (lane == 0 && kv > kmin)      // re-check vs updated min (monotone-safe)
                    heap_adjust(hI, hK, 0, K_, ib + l, kv);   // __pop_heap replace-top
                __syncwarp();
                kmin = hK[0];
            }
        }
    }

    // __sort_heap: extract min to back repeatedly -> descending values, heap tie order
    if (lane == 0)
        for (int len = K_; len > 1; len--) {
            int vI = hI[len-1]; unsigned vK = hK[len-1];
            hI[len-1] = hI[0]; hK[len-1] = hK[0];
            heap_adjust(hI, hK, 0, len - 1, vI, vK);
        }
    __syncwarp();
    for (int t = lane; t < K_; t += 32) {
        int idx = hI[t];
        g_topk[r*K_ + t] = idx;
        out[(size_t)B_*N_ + (size_t)B_*K_ + r*K_ + t] = (float)idx;
    }
}

// ------------------------- 6) build sequence [M, 2D] -------------------------
__global__ void k_build(const float* __restrict__ gnn, const float* __restrict__ E,
                        const int* __restrict__ bidx) {
    int m = blockIdx.x;
    int t = threadIdx.x;          // 256 threads
    int idx = g_topk[m];
    if (idx < 0 || idx >= N_) idx = 0;
    float val;
    if (t < 128) {
        int q = g_pos[idx];              // faithful non-globalized lookup
        if (q >= 0) val = gnn[(size_t)q*C_ + t];
        else        val = E[(size_t)idx*C_ + t];
    } else {
        int b = m / K_;
        val = g_lhs_proj[(size_t)bidx[b]*D_ + (t - 128)];
    }
    g_x[(size_t)m*C2_ + t] = val;
}

// ------------------------- 7) tiled GEMM Y = X[M,256] @ W[256,Nd] + b -------------------------
__global__ __launch_bounds__(256) void k_gemm(const float* __restrict__ X,
                                              const float* __restrict__ W,
                                              const float* __restrict__ bias,
                                              float* __restrict__ Y,
                                              int Nd, int relu) {
    __shared__ float Xs[32][132];
    __shared__ float Ws[32][68];
    int tid = threadIdx.x, tx = tid & 15, ty = tid >> 4;
    int n0 = blockIdx.x * 64, m0 = blockIdx.y * 128;
    float acc[8][4] = {};
    for (int kc = 0; kc < C2_; kc += 32) {
        #pragma unroll
        for (int v = 0; v < 4; v++) {
            int q = tid + v*256;
            int am = q >> 3, ak = q & 7;
            float4 t4 = *(const float4*)(X + (size_t)(m0+am)*C2_ + kc + ak*4);
            Xs[ak*4+0][am] = t4.x; Xs[ak*4+1][am] = t4.y;
            Xs[ak*4+2][am] = t4.z; Xs[ak*4+3][am] = t4.w;
        }
        #pragma unroll
        for (int v = 0; v < 2; v++) {
            int q = tid + v*256;
            int wk = q >> 4, n4 = q & 15;
            *(float4*)&Ws[wk][n4*4] = *(const float4*)(W + (size_t)(kc+wk)*Nd + n0 + n4*4);
        }
        __syncthreads();
        #pragma unroll
        for (int k = 0; k < 32; k++) {
            float4 a0 = *(const float4*)&Xs[k][ty*8];
            float4 a1 = *(const float4*)&Xs[k][ty*8+4];
            float4 w0 = *(const float4*)&Ws[k][tx*4];
            float av[8] = {a0.x,a0.y,a0.z,a0.w,a1.x,a1.y,a1.z,a1.w};
            #pragma unroll
            for (int i = 0; i < 8; i++) {
                acc[i][0] = __fmaf_rn(av[i], w0.x, acc[i][0]);
                acc[i][1] = __fmaf_rn(av[i], w0.y, acc[i][1]);
                acc[i][2] = __fmaf_rn(av[i], w0.z, acc[i][2]);
                acc[i][3] = __fmaf_rn(av[i], w0.w, acc[i][3]);
            }
        }
        __syncthreads();
    }
    #pragma unroll
    for (int i = 0; i < 8; i++) {
        int m = m0 + ty*8 + i;
        #pragma unroll
        for (int j = 0; j < 4; j++) {
            int n = n0 + tx*4 + j;
            float y = acc[i][j] + bias[n];
            if (relu) y = fmaxf(y, 0.f);
            Y[(size_t)m*Nd + n] = y;
        }
    }
}

// ------------------------- 8) attention: warp-per-query, K/V in smem -------------------------
#define ATT_FLOATS (K_*C2_ + K_*C2_ + 8*104)
#define ATT_SMEM   (ATT_FLOATS * 4)
__global__ __launch_bounds__(256) void k_attn() {
    extern __shared__ float sm[];
    float* Ks = sm;                       // [100][256] pre-scaled
    float* Vs = sm + K_*C2_;              // [100][256]
    float* sc = sm + 2*K_*C2_;            // [8][104]
    int b = blockIdx.x, t = threadIdx.x, w = t >> 5, lane = t & 31;
    const float* qp = g_q + (size_t)b*K_*C2_;
    const float* kp = g_k + (size_t)b*K_*C2_;
    const float* vp = g_v + (size_t)b*K_*C2_;
    for (int idx = t; idx < K_*C2_; idx += 256) {
        Ks[idx] = kp[idx] * 0.0625f;      // 1/sqrt(256)
        Vs[idx] = vp[idx];
    }
    __syncthreads();
    float* scw = sc + w*104;
    for (int qi = w; qi < K_; qi += 8) {
        const float4* qr = (const float4*)(qp + (size_t)qi*C2_ + lane*8);
        float4 q0 = qr[0], q1 = qr[1];
        for (int j = 0; j < K_; j++) {
            const float4* kr = (const float4*)(Ks + j*C2_ + lane*8);
            float4 k0 = kr[0], k1 = kr[1];
            float s = q0.x*k0.x + q0.y*k0.y + q0.z*k0.z + q0.w*k0.w
                    + q1.x*k1.x + q1.y*k1.y + q1.z*k1.z + q1.w*k1.w;
            #pragma unroll
            for (int o = 16; o; o >>= 1) s += __shfl_down_sync(0xffffffffu, s, o);
            if (lane == 0) scw[j] = s;
        }
        __syncwarp();
        float mx = -3.4e38f;
        for (int j = lane; j < K_; j += 32) mx = fmaxf(mx, scw[j]);
        #pragma unroll
        for (int o = 16; o; o >>= 1) mx = fmaxf(mx, __shfl_xor_sync(0xffffffffu, mx, o));
        float sum = 0.f;
        for (int j = lane; j < K_; j += 32) {
            float e = expf(scw[j] - mx);
            scw[j] = e;
            sum += e;
        }
        #pragma unroll
        for (int o = 16; o; o >>= 1) sum += __shfl_xor_sync(0xffffffffu, sum, o);
        float inv = 1.f / sum;
        for (int j = lane; j < K_; j += 32) scw[j] *= inv;
        __syncwarp();
        float acc[8] = {};
        for (int j = 0; j < K_; j++) {
            float p = scw[j];
            const float4* vr = (const float4*)(Vs + j*C2_ + lane*8);
            float4 v0 = vr[0], v1 = vr[1];
            acc[0] += p*v0.x; acc[1] += p*v0.y; acc[2] += p*v0.z; acc[3] += p*v0.w;
            acc[4] += p*v1.x; acc[5] += p*v1.y; acc[6] += p*v1.z; acc[7] += p*v1.w;
        }
        float* op = g_o + ((size_t)b*K_ + qi)*C2_ + lane*8;
        *(float4*)op     = make_float4(acc[0], acc[1], acc[2], acc[3]);
        *(float4*)(op+4) = make_float4(acc[4], acc[5], acc[6], acc[7]);
        __syncwarp();
    }
}

// ------------------------- 9) LayerNorm: Y = LN(A + R)*g + b -------------------------
__global__ void k_ln(const float* __restrict__ A, const float* __restrict__ R,
                     const float* __restrict__ g, const float* __restrict__ bb,
                     float* __restrict__ Y) {
    __shared__ float red[256];
    __shared__ float s_m, s_r;
    int m = blockIdx.x, t = threadIdx.x;
    float x = A[(size_t)m*C2_ + t] + R[(size_t)m*C2_ + t];
    red[t] = x; __syncthreads();
    for (int s = 128; s; s >>= 1) { if (t < s) red[t] += red[t+s]; __syncthreads(); }
    if (t == 0) s_m = red[0] * (1.f/256.f);
    __syncthreads();
    float d = x - s_m;
    red[t] = d*d; __syncthreads();
    for (int s = 128; s; s >>= 1) { if (t < s) red[t] += red[t+s]; __syncthreads(); }
    if (t == 0) s_r = rsqrtf(red[0] * (1.f/256.f) + 1e-5f);
    __syncthreads();
    Y[(size_t)m*C2_ + t] = d * s_r * g[t] + bb[t];
}

// ------------------------- 10) tr_logits = dot(x[:,128:], tr) -------------------------
__global__ void k_final(float* __restrict__ out) {
    int m = blockIdx.x*8 + (threadIdx.x >> 5);
    int lane = threadIdx.x & 31;
    float4 a = *(const float4*)&g_x[(size_t)m*C2_ + 128 + lane*4];
    float4 c = *(const float4*)&g_tr[(size_t)m*D_ + lane*4];
    float s = a.x*c.x + a.y*c.y + a.z*c.z + a.w*c.w;
    #pragma unroll
    for (int o = 16; o; o >>= 1) s += __shfl_down_sync(0xffffffffu, s, o);
    if (lane == 0) out[(size_t)B_*N_ + m] = s;
}

// ------------------------- launch -------------------------
extern "C" void kernel_launch(void* const* d_in, const int* in_sizes, int n_in,
                              void* d_out, int out_size) {
    const float* lhs   = (const float*)d_in[0];
    const float* gnn   = (const float*)d_in[1];
    const int*   ridx  = (const int*)  d_in[2];
    const int*   bidx  = (const int*)  d_in[3];
    const float* E     = (const float*)d_in[4];
    const float* wproj = (const float*)d_in[5];
    const float* bproj = (const float*)d_in[6];
    const float* whead = (const float*)d_in[7];
    const float* bhead = (const float*)d_in[8];
    const float* woe   = (const float*)d_in[9];
    const float* boe   = (const float*)d_in[10];
    const float* woi   = (const float*)d_in[11];
    const float* boi   = (const float*)d_in[12];
    const float* wq    = (const float*)d_in[13];
    const float* bq    = (const float*)d_in[14];
    const float* wk    = (const float*)d_in[15];
    const float* bk    = (const float*)d_in[16];
    const float* wv    = (const float*)d_in[17];
    const float* bv    = (const float*)d_in[18];
    const float* wo    = (const float*)d_in[19];
    const float* bo    = (const float*)d_in[20];
    const float* ln1g  = (const float*)d_in[21];
    const float* ln1b  = (const float*)d_in[22];
    const float* wf    = (const float*)d_in[23];
    const float* bf    = (const float*)d_in[24];
    const float* ln2g  = (const float*)d_in[25];
    const float* ln2b  = (const float*)d_in[26];
    const float* wtr   = (const float*)d_in[27];
    const float* btr   = (const float*)d_in[28];
    float* out = (float*)d_out;

    cudaFuncSetAttribute(k_attn, cudaFuncAttributeMaxDynamicSharedMemorySize, ATT_SMEM);

    float *x, *q, *k, *v, *o, *op, *h, *f, *x2, *tr;
    cudaGetSymbolAddress((void**)&x,  g_x);
    cudaGetSymbolAddress((void**)&q,  g_q);
    cudaGetSymbolAddress((void**)&k,  g_k);
    cudaGetSymbolAddress((void**)&v,  g_v);
    cudaGetSymbolAddress((void**)&o,  g_o);
    cudaGetSymbolAddress((void**)&op, g_op);
    cudaGetSymbolAddress((void**)&h,  g_h);
    cudaGetSymbolAddress((void**)&f,  g_f);
    cudaGetSymbolAddress((void**)&x2, g_x2);
    cudaGetSymbolAddress((void**)&tr, g_tr);

    k_initpos<<<25000, 1024>>>();
    k_lhsproj<<<B_, 128>>>(lhs, wproj, bproj, woe, boe, woi, boi);
    k_idgnn<<<NID_/4, 128>>>(gnn, lhs, bidx, ridx, whead, bhead);
    k_embgnn<<<dim3((N_+63)/64, 2), 256>>>(E, out);
    k_scatter<<<NID_/256, 256>>>(bidx, ridx, out);
    k_topk<<<B_/8, 256>>>(out, out);
    k_build<<<M_, 256>>>(gnn, E, bidx);

    dim3 g4(4, M_/128), g2(2, M_/128);
    k_gemm<<<g4, 256>>>(x,  wq, bq, q,  C2_, 0);
    k_gemm<<<g4, 256>>>(x,  wk, bk, k,  C2_, 0);
    k_gemm<<<g4, 256>>>(x,  wv, bv, v,  C2_, 0);
    k_attn<<<B_, 256, ATT_SMEM>>>();
    k_gemm<<<g4, 256>>>(o,  wo, bo, op, C2_, 0);
    k_ln<<<M_, 256>>>(x, op, ln1g, ln1b, h);
    k_gemm<<<g4, 256>>>(h,  wf, bf, f,  C2_, 1);
    k_ln<<<M_, 256>>>(h, f, ln2g, ln2b, x2);
    k_gemm<<<g2, 256>>>(x2, wtr, btr, tr, D_, 0);
    k_final<<<M_/8, 256>>>(out);
}

// round 15
// speedup vs baseline: 1.0954x; 1.0954x over previous
#include <cuda_runtime.h>
#include <math.h>

#define B_    256
#define C_    128
#define D_    128
#define N_    100000
#define NID_  131072
#define K_    100
#define C2_   256
#define M_    (B_*K_)

// ------------------------- scratch (device globals) -------------------------
__device__ float g_lhs_proj[B_*D_];
__device__ float g_emb_off[B_];
__device__ float g_idg_off[B_];
__device__ float g_idgnn[NID_];
__device__ int   g_pos[B_*N_];          // 25.6M ints
__device__ int   g_topk[M_];
__device__ float g_x [M_*C2_];
__device__ float g_q [M_*C2_];
__device__ float g_k [M_*C2_];
__device__ float g_v [M_*C2_];
__device__ float g_o [M_*C2_];
__device__ float g_op[M_*C2_];
__device__ float g_h [M_*C2_];
__device__ float g_f [M_*C2_];
__device__ float g_x2[M_*C2_];
__device__ float g_tr[M_*D_];

// ------------------------- 0) init pos table (vectorized) -------------------------
__global__ void k_initpos() {
    int i = blockIdx.x * blockDim.x + threadIdx.x;   // 6250 x 1024 x int4 = 25.6M
    ((int4*)g_pos)[i] = make_int4(-1, -1, -1, -1);
}

// ------------------------- 1) lhs_proj + offsets (strict sequential; FROZEN) -------------------------
__global__ void k_lhsproj(const float* __restrict__ lhs, const float* __restrict__ wp,
                          const float* __restrict__ bp, const float* __restrict__ woe,
                          const float* __restrict__ boe, const float* __restrict__ woi,
                          const float* __restrict__ boi) {
    __shared__ float s_l[C_];
    __shared__ float sacc[C_];
    int b = blockIdx.x, t = threadIdx.x;     // 128 threads
    s_l[t] = lhs[b*C_ + t];
    __syncthreads();
    float acc = 0.f;
    for (int c = 0; c < C_; c++) acc = __fmaf_rn(s_l[c], wp[c*D_ + t], acc);
    acc = __fadd_rn(acc, bp[t]);
    g_lhs_proj[b*D_ + t] = acc;
    sacc[t] = acc;
    __syncthreads();
    if (t == 0) {
        float eo = 0.f;
        for (int c = 0; c < C_; c++) eo = __fmaf_rn(sacc[c], woe[c], eo);
        g_emb_off[b] = __fadd_rn(eo, boe[0]);
        float io = 0.f;
        for (int c = 0; c < C_; c++) io = __fmaf_rn(sacc[c], woi[c], io);
        g_idg_off[b] = __fadd_rn(io, boi[0]);
    }
}

// ------------------------- 2) idgnn logits + pos winners (FROZEN math) -------------------------
__global__ __launch_bounds__(128) void k_idgnn(const float* __restrict__ gnn,
                        const float* __restrict__ lhs,
                        const int* __restrict__ bidx, const int* __restrict__ ridx,
                        const float* __restrict__ wh, const float* __restrict__ bh) {
    __shared__ float sW[C_];
    __shared__ float sG[4][C_];
    __shared__ float sL[4][C_];
    int t = threadIdx.x, w = t >> 5, lane = t & 31;
    sW[t] = wh[t];
    int node = blockIdx.x * 4 + w;
    if (node >= NID_) return;
    int bt = bidx[node];
    for (int c = lane; c < C_; c += 32) {
        sG[w][c] = gnn[(size_t)node*C_ + c];
        sL[w][c] = lhs[(size_t)bt*C_ + c];
    }
    __syncthreads();
    if (lane == 0) {
        float sh = 0.f;
        for (int c = 0; c < C_; c++) sh = __fmaf_rn(sG[w][c], sW[c], sh);
        float sl = 0.f;
        for (int c = 0; c < C_; c++) {
            float p = __fmul_rn(sL[w][c], sG[w][c]);
            sl = __fadd_rn(sl, p);
        }
        float v = __fadd_rn(__fadd_rn(__fadd_rn(sh, bh[0]), sl), g_idg_off[bt]);
        g_idgnn[node] = v;
        atomicMax(&g_pos[(size_t)bt*N_ + ridx[node]], node);   // last-update-wins
    }
}

// ------------------------- 3) embgnn GEMM (FROZEN — validated by output 0) -------------------------
__global__ __launch_bounds__(256) void k_embgnn(const float* __restrict__ E,
                                                float* __restrict__ out) {
    __shared__ float As[32][132];
    __shared__ float Es[32][68];
    int tid = threadIdx.x;
    int tx = tid & 15, ty = tid >> 4;
    int n0 = blockIdx.x * 64, m0 = blockIdx.y * 128;
    float acc[8][4] = {};
    for (int kc = 0; kc < D_; kc += 32) {
        #pragma unroll
        for (int v = 0; v < 4; v++) {
            int q = tid + v*256;
            int am = q >> 3, ak = q & 7;
            float4 t4 = *(const float4*)(g_lhs_proj + (size_t)(m0+am)*D_ + kc + ak*4);
            As[ak*4+0][am] = t4.x; As[ak*4+1][am] = t4.y;
            As[ak*4+2][am] = t4.z; As[ak*4+3][am] = t4.w;
        }
        #pragma unroll
        for (int v = 0; v < 2; v++) {
            int q = tid + v*256;
            int en = q >> 3, ek = q & 7;
            int n = n0 + en;
            float4 t4 = make_float4(0.f,0.f,0.f,0.f);
            if (n < N_) t4 = *(const float4*)(E + (size_t)n*D_ + kc + ek*4);
            Es[ek*4+0][en] = t4.x; Es[ek*4+1][en] = t4.y;
            Es[ek*4+2][en] = t4.z; Es[ek*4+3][en] = t4.w;
        }
        __syncthreads();
        #pragma unroll
        for (int k = 0; k < 32; k++) {
            float4 a0 = *(const float4*)&As[k][ty*8];
            float4 a1 = *(const float4*)&As[k][ty*8+4];
            float4 w0 = *(const float4*)&Es[k][tx*4];
            float av[8] = {a0.x,a0.y,a0.z,a0.w,a1.x,a1.y,a1.z,a1.w};
            #pragma unroll
            for (int i = 0; i < 8; i++) {
                acc[i][0] = __fmaf_rn(av[i], w0.x, acc[i][0]);
                acc[i][1] = __fmaf_rn(av[i], w0.y, acc[i][1]);
                acc[i][2] = __fmaf_rn(av[i], w0.z, acc[i][2]);
                acc[i][3] = __fmaf_rn(av[i], w0.w, acc[i][3]);
            }
        }
        __syncthreads();
    }
    #pragma unroll
    for (int i = 0; i < 8; i++) {
        int m = m0 + ty*8 + i;
        float off = g_emb_off[m];
        #pragma unroll
        for (int j = 0; j < 4; j++) {
            int n = n0 + tx*4 + j;
            if (n < N_) out[(size_t)m*N_ + n] = __fadd_rn(acc[i][j], off);
        }
    }
}

// ------------------------- 4) scatter winners (FROZEN) -------------------------
__global__ void k_scatter(const int* __restrict__ bidx, const int* __restrict__ ridx,
                          float* __restrict__ out) {
    int i = blockIdx.x * blockDim.x + threadIdx.x;
    if (i >= NID_) return;
    size_t slot = (size_t)bidx[i]*N_ + ridx[i];
    if (g_pos[slot] == i) out[slot] = g_idgnn[i];
}

// ------------------------- 5) top-K: EXACT std::partial_sort emulation (FROZEN semantics) -------------------------
// Same heap mechanics as R14 (validated). Speedups: 16-deep prefetch + per-window
// warp-max skip. kmin is monotone non-decreasing, so skipping a window whose max
// key <= current kmin is EXACTLY equivalent (no element of it could ever insert).
__device__ __forceinline__ unsigned fkey(float x) {
    unsigned u = __float_as_uint(x);
    return (u & 0x80000000u) ? ~u : (u | 0x80000000u);
}

__device__ void heap_adjust(int* hI, unsigned* hK, int hole, int len,
                            int vI, unsigned vK) {
    int top = hole;
    int sc = hole;
    while (sc < (len - 1) / 2) {
        sc = 2 * (sc + 1);
        if (hK[sc] > hK[sc - 1]) sc--;          // pick cmp-greater child (smaller key)
        hI[hole] = hI[sc]; hK[hole] = hK[sc];
        hole = sc;
    }
    if ((len & 1) == 0 && sc == (len - 2) / 2) {
        sc = 2 * (sc + 1);
        hI[hole] = hI[sc - 1]; hK[hole] = hK[sc - 1];
        hole = sc - 1;
    }
    while (hole > top) {                         // __push_heap
        int par = (hole - 1) >> 1;
        if (hK[par] > vK) { hI[hole] = hI[par]; hK[hole] = hK[par]; hole = par; }
        else break;
    }
    hI[hole] = vI; hK[hole] = vK;
}

__global__ __launch_bounds__(256) void k_topk(const float* __restrict__ logits,
                                              float* __restrict__ out) {
    __shared__ int      sI[8][K_];
    __shared__ unsigned sK[8][K_];
    int w = threadIdx.x >> 5, lane = threadIdx.x & 31;
    int r = blockIdx.x * 8 + w;
    const float* row = logits + (size_t)r * N_;
    int* hI = sI[w]; unsigned* hK = sK[w];

    for (int i = lane; i < K_; i += 32) { hI[i] = i; hK[i] = fkey(row[i]); }
    __syncwarp();
    if (lane == 0)
        for (int p = (K_ - 2) / 2; p >= 0; p--)
            heap_adjust(hI, hK, p, K_, hI[p], hK[p]);
    __syncwarp();
    unsigned kmin = hK[0];

    // stream i = K..N-1 in order, 512-wide windows with 16-deep prefetch
    for (int base = K_; base < N_; base += 512) {
        unsigned kk[16];
        #pragma unroll
        for (int j = 0; j < 16; j++) {
            int i = base + j*32 + lane;
            kk[j] = (i < N_) ? fkey(row[i]) : 0u;
        }
        unsigned wm = kk[0];
        #pragma unroll
        for (int j = 1; j < 16; j++) wm = (kk[j] > wm) ? kk[j] : wm;
        if (__ballot_sync(0xffffffffu, wm > kmin) == 0u) continue;  // exact skip
        #pragma unroll
        for (int j = 0; j < 16; j++) {
            int ib = base + j*32;
            if (ib >= N_) break;
            unsigned m = __ballot_sync(0xffffffffu, (ib + lane) < N_ && kk[j] > kmin);
            while (m) {
                int l = __ffs(m) - 1; m &= m - 1;
                unsigned kv = __shfl_sync(0xffffffffu, kk[j], l);
                if (lane == 0 && kv > kmin)      // re-check vs updated min (monotone-safe)
                    heap_adjust(hI, hK, 0, K_, ib + l, kv);   // __pop_heap replace-top
                __syncwarp();
                kmin = hK[0];
            }
        }
    }

    // __sort_heap
    if (lane == 0)
        for (int len = K_; len > 1; len--) {
            int vI = hI[len-1]; unsigned vK = hK[len-1];
            hI[len-1] = hI[0]; hK[len-1] = hK[0];
            heap_adjust(hI, hK, 0, len - 1, vI, vK);
        }
    __syncwarp();
    for (int t = lane; t < K_; t += 32) {
        int idx = hI[t];
        g_topk[r*K_ + t] = idx;
        out[(size_t)B_*N_ + (size_t)B_*K_ + r*K_ + t] = (float)idx;
    }
}

// ------------------------- 6) build sequence [M, 2D] -------------------------
__global__ void k_build(const float* __restrict__ gnn, const float* __restrict__ E,
                        const int* __restrict__ bidx) {
    int m = blockIdx.x;
    int t = threadIdx.x;          // 256 threads
    int idx = g_topk[m];
    if (idx < 0 || idx >= N_) idx = 0;
    float val;
    if (t < 128) {
        int q = g_pos[idx];              // faithful non-globalized lookup
        if (q >= 0) val = gnn[(size_t)q*C_ + t];
        else        val = E[(size_t)idx*C_ + t];
    } else {
        int b = m / K_;
        val = g_lhs_proj[(size_t)bidx[b]*D_ + (t - 128)];
    }
    g_x[(size_t)m*C2_ + t] = val;
}

// ------------------------- 7a) fused QKV GEMM: z selects (W,b,Y) -------------------------
__global__ __launch_bounds__(256) void k_gemm3(const float* __restrict__ X,
                                               const float* __restrict__ W0,
                                               const float* __restrict__ W1,
                                               const float* __restrict__ W2,
                                               const float* __restrict__ b0,
                                               const float* __restrict__ b1,
                                               const float* __restrict__ b2,
                                               float* __restrict__ Y0,
                                               float* __restrict__ Y1,
                                               float* __restrict__ Y2) {
    const float* W = (blockIdx.z == 0) ? W0 : (blockIdx.z == 1) ? W1 : W2;
    const float* bias = (blockIdx.z == 0) ? b0 : (blockIdx.z == 1) ? b1 : b2;
    float* Y = (blockIdx.z == 0) ? Y0 : (blockIdx.z == 1) ? Y1 : Y2;
    __shared__ float Xs[32][132];
    __shared__ float Ws[32][68];
    int tid = threadIdx.x, tx = tid & 15, ty = tid >> 4;
    int n0 = blockIdx.x * 64, m0 = blockIdx.y * 128;
    float acc[8][4] = {};
    for (int kc = 0; kc < C2_; kc += 32) {
        #pragma unroll
        for (int v = 0; v < 4; v++) {
            int q = tid + v*256;
            int am = q >> 3, ak = q & 7;
            float4 t4 = *(const float4*)(X + (size_t)(m0+am)*C2_ + kc + ak*4);
            Xs[ak*4+0][am] = t4.x; Xs[ak*4+1][am] = t4.y;
            Xs[ak*4+2][am] = t4.z; Xs[ak*4+3][am] = t4.w;
        }
        #pragma unroll
        for (int v = 0; v < 2; v++) {
            int q = tid + v*256;
            int wk = q >> 4, n4 = q & 15;
            *(float4*)&Ws[wk][n4*4] = *(const float4*)(W + (size_t)(kc+wk)*C2_ + n0 + n4*4);
        }
        __syncthreads();
        #pragma unroll
        for (int k = 0; k < 32; k++) {
            float4 a0 = *(const float4*)&Xs[k][ty*8];
            float4 a1 = *(const float4*)&Xs[k][ty*8+4];
            float4 w0 = *(const float4*)&Ws[k][tx*4];
            float av[8] = {a0.x,a0.y,a0.z,a0.w,a1.x,a1.y,a1.z,a1.w};
            #pragma unroll
            for (int i = 0; i < 8; i++) {
                acc[i][0] = __fmaf_rn(av[i], w0.x, acc[i][0]);
                acc[i][1] = __fmaf_rn(av[i], w0.y, acc[i][1]);
                acc[i][2] = __fmaf_rn(av[i], w0.z, acc[i][2]);
                acc[i][3] = __fmaf_rn(av[i], w0.w, acc[i][3]);
            }
        }
        __syncthreads();
    }
    #pragma unroll
    for (int i = 0; i < 8; i++) {
        int m = m0 + ty*8 + i;
        #pragma unroll
        for (int j = 0; j < 4; j++) {
            int n = n0 + tx*4 + j;
            Y[(size_t)m*C2_ + n] = acc[i][j] + bias[n];
        }
    }
}

// ------------------------- 7b) generic tiled GEMM -------------------------
__global__ __launch_bounds__(256) void k_gemm(const float* __restrict__ X,
                                              const float* __restrict__ W,
                                              const float* __restrict__ bias,
                                              float* __restrict__ Y,
                                              int Nd, int relu) {
    __shared__ float Xs[32][132];
    __shared__ float Ws[32][68];
    int tid = threadIdx.x, tx = tid & 15, ty = tid >> 4;
    int n0 = blockIdx.x * 64, m0 = blockIdx.y * 128;
    float acc[8][4] = {};
    for (int kc = 0; kc < C2_; kc += 32) {
        #pragma unroll
        for (int v = 0; v < 4; v++) {
            int q = tid + v*256;
            int am = q >> 3, ak = q & 7;
            float4 t4 = *(const float4*)(X + (size_t)(m0+am)*C2_ + kc + ak*4);
            Xs[ak*4+0][am] = t4.x; Xs[ak*4+1][am] = t4.y;
            Xs[ak*4+2][am] = t4.z; Xs[ak*4+3][am] = t4.w;
        }
        #pragma unroll
        for (int v = 0; v < 2; v++) {
            int q = tid + v*256;
            int wk = q >> 4, n4 = q & 15;
            *(float4*)&Ws[wk][n4*4] = *(const float4*)(W + (size_t)(kc+wk)*Nd + n0 + n4*4);
        }
        __syncthreads();
        #pragma unroll
        for (int k = 0; k < 32; k++) {
            float4 a0 = *(const float4*)&Xs[k][ty*8];
            float4 a1 = *(const float4*)&Xs[k][ty*8+4];
            float4 w0 = *(const float4*)&Ws[k][tx*4];
            float av[8] = {a0.x,a0.y,a0.z,a0.w,a1.x,a1.y,a1.z,a1.w};
            #pragma unroll
            for (int i = 0; i < 8; i++) {
                acc[i][0] = __fmaf_rn(av[i], w0.x, acc[i][0]);
                acc[i][1] = __fmaf_rn(av[i], w0.y, acc[i][1]);
                acc[i][2] = __fmaf_rn(av[i], w0.z, acc[i][2]);
                acc[i][3] = __fmaf_rn(av[i], w0.w, acc[i][3]);
            }
        }
        __syncthreads();
    }
    #pragma unroll
    for (int i = 0; i < 8; i++) {
        int m = m0 + ty*8 + i;
        #pragma unroll
        for (int j = 0; j < 4; j++) {
            int n = n0 + tx*4 + j;
            float y = acc[i][j] + bias[n];
            if (relu) y = fmaxf(y, 0.f);
            Y[(size_t)m*Nd + n] = y;
        }
    }
}

// ------------------------- 8) attention: conflict-free lane*4 ownership -------------------------
#define ATT_FLOATS (K_*C2_ + K_*C2_ + 8*104)
#define ATT_SMEM   (ATT_FLOATS * 4)
__global__ __launch_bounds__(256) void k_attn() {
    extern __shared__ float sm[];
    float* Ks = sm;                       // [100][256] pre-scaled
    float* Vs = sm + K_*C2_;              // [100][256]
    float* sc = sm + 2*K_*C2_;            // [8][104]
    int b = blockIdx.x, t = threadIdx.x, w = t >> 5, lane = t & 31;
    const float* qp = g_q + (size_t)b*K_*C2_;
    const float* kp = g_k + (size_t)b*K_*C2_;
    const float* vp = g_v + (size_t)b*K_*C2_;
    for (int idx = t; idx < K_*C2_; idx += 256) {
        Ks[idx] = kp[idx] * 0.0625f;      // 1/sqrt(256)
        Vs[idx] = vp[idx];
    }
    __syncthreads();
    float* scw = sc + w*104;
    for (int qi = w; qi < K_; qi += 8) {
        // lane owns dims [lane*4, +4) and [128+lane*4, +4): LDS.128 conflict-free
        float4 q0 = *(const float4*)(qp + (size_t)qi*C2_ + lane*4);
        float4 q1 = *(const float4*)(qp + (size_t)qi*C2_ + 128 + lane*4);
        for (int j = 0; j < K_; j++) {
            float4 k0 = *(const float4*)&Ks[j*C2_ + lane*4];
            float4 k1 = *(const float4*)&Ks[j*C2_ + 128 + lane*4];
            float s = q0.x*k0.x + q0.y*k0.y + q0.z*k0.z + q0.w*k0.w
                    + q1.x*k1.x + q1.y*k1.y + q1.z*k1.z + q1.w*k1.w;
            #pragma unroll
            for (int o = 16; o; o >>= 1) s += __shfl_down_sync(0xffffffffu, s, o);
            if (lane == 0) scw[j] = s;
        }
        __syncwarp();
        float mx = -3.4e38f;
        for (int j = lane; j < K_; j += 32) mx = fmaxf(mx, scw[j]);
        #pragma unroll
        for (int o = 16; o; o >>= 1) mx = fmaxf(mx, __shfl_xor_sync(0xffffffffu, mx, o));
        float sum = 0.f;
        for (int j = lane; j < K_; j += 32) {
            float e = expf(scw[j] - mx);
            scw[j] = e;
            sum += e;
        }
        #pragma unroll
        for (int o = 16; o; o >>= 1) sum += __shfl_xor_sync(0xffffffffu, sum, o);
        float inv = 1.f / sum;
        for (int j = lane; j < K_; j += 32) scw[j] *= inv;
        __syncwarp();
        float a0x=0.f,a0y=0.f,a0z=0.f,a0w=0.f,a1x=0.f,a1y=0.f,a1z=0.f,a1w=0.f;
        for (int j = 0; j < K_; j++) {
            float p = scw[j];
            float4 v0 = *(const float4*)&Vs[j*C2_ + lane*4];
            float4 v1 = *(const float4*)&Vs[j*C2_ + 128 + lane*4];
            a0x += p*v0.x; a0y += p*v0.y; a0z += p*v0.z; a0w += p*v0.w;
            a1x += p*v1.x; a1y += p*v1.y; a1z += p*v1.z; a1w += p*v1.w;
        }
        float* op = g_o + ((size_t)b*K_ + qi)*C2_;
        *(float4*)(op + lane*4)       = make_float4(a0x, a0y, a0z, a0w);
        *(float4*)(op + 128 + lane*4) = make_float4(a1x, a1y, a1z, a1w);
        __syncwarp();
    }
}

// ------------------------- 9) LayerNorm: Y = LN(A + R)*g + b -------------------------
__global__ void k_ln(const float* __restrict__ A, const float* __restrict__ R,
                     const float* __restrict__ g, const float* __restrict__ bb,
                     float* __restrict__ Y) {
    __shared__ float red[256];
    __shared__ float s_m, s_r;
    int m = blockIdx.x, t = threadIdx.x;
    float x = A[(size_t)m*C2_ + t] + R[(size_t)m*C2_ + t];
    red[t] = x; __syncthreads();
    for (int s = 128; s; s >>= 1) { if (t < s) red[t] += red[t+s]; __syncthreads(); }
    if (t == 0) s_m = red[0] * (1.f/256.f);
    __syncthreads();
    float d = x - s_m;
    red[t] = d*d; __syncthreads();
    for (int s = 128; s; s >>= 1) { if (t < s) red[t] += red[t+s]; __syncthreads(); }
    if (t == 0) s_r = rsqrtf(red[0] * (1.f/256.f) + 1e-5f);
    __syncthreads();
    Y[(size_t)m*C2_ + t] = d * s_r * g[t] + bb[t];
}

// ------------------------- 10) tr_logits = dot(x[:,128:], tr) -------------------------
__global__ void k_final(float* __restrict__ out) {
    int m = blockIdx.x*8 + (threadIdx.x >> 5);
    int lane = threadIdx.x & 31;
    float4 a = *(const float4*)&g_x[(size_t)m*C2_ + 128 + lane*4];
    float4 c = *(const float4*)&g_tr[(size_t)m*D_ + lane*4];
    float s = a.x*c.x + a.y*c.y + a.z*c.z + a.w*c.w;
    #pragma unroll
    for (int o = 16; o; o >>= 1) s += __shfl_down_sync(0xffffffffu, s, o);
    if (lane == 0) out[(size_t)B_*N_ + m] = s;
}

// ------------------------- launch -------------------------
extern "C" void kernel_launch(void* const* d_in, const int* in_sizes, int n_in,
                              void* d_out, int out_size) {
    const float* lhs   = (const float*)d_in[0];
    const float* gnn   = (const float*)d_in[1];
    const int*   ridx  = (const int*)  d_in[2];
    const int*   bidx  = (const int*)  d_in[3];
    const float* E     = (const float*)d_in[4];
    const float* wproj = (const float*)d_in[5];
    const float* bproj = (const float*)d_in[6];
    const float* whead = (const float*)d_in[7];
    const float* bhead = (const float*)d_in[8];
    const float* woe   = (const float*)d_in[9];
    const float* boe   = (const float*)d_in[10];
    const float* woi   = (const float*)d_in[11];
    const float* boi   = (const float*)d_in[12];
    const float* wq    = (const float*)d_in[13];
    const float* bq    = (const float*)d_in[14];
    const float* wk    = (const float*)d_in[15];
    const float* bk    = (const float*)d_in[16];
    const float* wv    = (const float*)d_in[17];
    const float* bv    = (const float*)d_in[18];
    const float* wo    = (const float*)d_in[19];
    const float* bo    = (const float*)d_in[20];
    const float* ln1g  = (const float*)d_in[21];
    const float* ln1b  = (const float*)d_in[22];
    const float* wf    = (const float*)d_in[23];
    const float* bf    = (const float*)d_in[24];
    const float* ln2g  = (const float*)d_in[25];
    const float* ln2b  = (const float*)d_in[26];
    const float* wtr   = (const float*)d_in[27];
    const float* btr   = (const float*)d_in[28];
    float* out = (float*)d_out;

    cudaFuncSetAttribute(k_attn, cudaFuncAttributeMaxDynamicSharedMemorySize, ATT_SMEM);

    float *x, *q, *k, *v, *o, *op, *h, *f, *x2, *tr;
    cudaGetSymbolAddress((void**)&x,  g_x);
    cudaGetSymbolAddress((void**)&q,  g_q);
    cudaGetSymbolAddress((void**)&k,  g_k);
    cudaGetSymbolAddress((void**)&v,  g_v);
    cudaGetSymbolAddress((void**)&o,  g_o);
    cudaGetSymbolAddress((void**)&op, g_op);
    cudaGetSymbolAddress((void**)&h,  g_h);
    cudaGetSymbolAddress((void**)&f,  g_f);
    cudaGetSymbolAddress((void**)&x2, g_x2);
    cudaGetSymbolAddress((void**)&tr, g_tr);

    k_initpos<<<6250, 1024>>>();
    k_lhsproj<<<B_, 128>>>(lhs, wproj, bproj, woe, boe, woi, boi);
    k_idgnn<<<NID_/4, 128>>>(gnn, lhs, bidx, ridx, whead, bhead);
    k_embgnn<<<dim3((N_+63)/64, 2), 256>>>(E, out);
    k_scatter<<<NID_/256, 256>>>(bidx, ridx, out);
    k_topk<<<B_/8, 256>>>(out, out);
    k_build<<<M_, 256>>>(gnn, E, bidx);

    dim3 g4(4, M_/128), g2(2, M_/128), g43(4, M_/128, 3);
    k_gemm3<<<g43, 256>>>(x, wq, wk, wv, bq, bk, bv, q, k, v);
    k_attn<<<B_, 256, ATT_SMEM>>>();
    k_gemm<<<g4, 256>>>(o,  wo, bo, op, C2_, 0);
    k_ln<<<M_, 256>>>(x, op, ln1g, ln1b, h);
    k_gemm<<<g4, 256>>>(h,  wf, bf, f,  C2_, 1);
    k_ln<<<M_, 256>>>(h, f, ln2g, ln2b, x2);
    k_gemm<<<g2, 256>>>(x2, wtr, btr, tr, D_, 0);
    k_final<<<M_/8, 256>>>(out);
}

// round 16
// speedup vs baseline: 1.2079x; 1.1027x over previous
#include <cuda_runtime.h>
#include <math.h>

#define B_    256
#define C_    128
#define D_    128
#define N_    100000
#define NID_  131072
#define K_    100
#define C2_   256
#define M_    (B_*K_)

// ------------------------- scratch (device globals) -------------------------
__device__ float g_lhs_proj[B_*D_];
__device__ float g_emb_off[B_];
__device__ float g_idg_off[B_];
__device__ float g_idgnn[NID_];
__device__ int   g_pos[B_*N_];          // 25.6M ints
__device__ int   g_topk[M_];
__device__ float g_x [M_*C2_];
__device__ float g_q [M_*C2_];
__device__ float g_k [M_*C2_];
__device__ float g_v [M_*C2_];
__device__ float g_o [M_*C2_];
__device__ float g_op[M_*C2_];
__device__ float g_h [M_*C2_];
__device__ float g_f [M_*C2_];
__device__ float g_x2[M_*C2_];
__device__ float g_tr[M_*D_];
__device__ float g_att[B_*K_*104];      // attention probabilities scratch

// ------------------------- 1) lhs_proj + offsets (FROZEN) -------------------------
__global__ void k_lhsproj(const float* __restrict__ lhs, const float* __restrict__ wp,
                          const float* __restrict__ bp, const float* __restrict__ woe,
                          const float* __restrict__ boe, const float* __restrict__ woi,
                          const float* __restrict__ boi) {
    __shared__ float s_l[C_];
    __shared__ float sacc[C_];
    int b = blockIdx.x, t = threadIdx.x;     // 128 threads
    s_l[t] = lhs[b*C_ + t];
    __syncthreads();
    float acc = 0.f;
    for (int c = 0; c < C_; c++) acc = __fmaf_rn(s_l[c], wp[c*D_ + t], acc);
    acc = __fadd_rn(acc, bp[t]);
    g_lhs_proj[b*D_ + t] = acc;
    sacc[t] = acc;
    __syncthreads();
    if (t == 0) {
        float eo = 0.f;
        for (int c = 0; c < C_; c++) eo = __fmaf_rn(sacc[c], woe[c], eo);
        g_emb_off[b] = __fadd_rn(eo, boe[0]);
        float io = 0.f;
        for (int c = 0; c < C_; c++) io = __fmaf_rn(sacc[c], woi[c], io);
        g_idg_off[b] = __fadd_rn(io, boi[0]);
    }
}

// ------------------------- 2) idgnn logits + pos winners (FROZEN) -------------------------
__global__ __launch_bounds__(128) void k_idgnn(const float* __restrict__ gnn,
                        const float* __restrict__ lhs,
                        const int* __restrict__ bidx, const int* __restrict__ ridx,
                        const float* __restrict__ wh, const float* __restrict__ bh) {
    __shared__ float sW[C_];
    __shared__ float sG[4][C_];
    __shared__ float sL[4][C_];
    int t = threadIdx.x, w = t >> 5, lane = t & 31;
    sW[t] = wh[t];
    int node = blockIdx.x * 4 + w;
    if (node >= NID_) return;
    int bt = bidx[node];
    for (int c = lane; c < C_; c += 32) {
        sG[w][c] = gnn[(size_t)node*C_ + c];
        sL[w][c] = lhs[(size_t)bt*C_ + c];
    }
    __syncthreads();
    if (lane == 0) {
        float sh = 0.f;
        for (int c = 0; c < C_; c++) sh = __fmaf_rn(sG[w][c], sW[c], sh);
        float sl = 0.f;
        for (int c = 0; c < C_; c++) {
            float p = __fmul_rn(sL[w][c], sG[w][c]);
            sl = __fadd_rn(sl, p);
        }
        float v = __fadd_rn(__fadd_rn(__fadd_rn(sh, bh[0]), sl), g_idg_off[bt]);
        g_idgnn[node] = v;
        atomicMax(&g_pos[(size_t)bt*N_ + ridx[node]], node);   // last-update-wins
    }
}

// ------------------------- 3) embgnn GEMM (FROZEN — validated) -------------------------
__global__ __launch_bounds__(256) void k_embgnn(const float* __restrict__ E,
                                                float* __restrict__ out) {
    __shared__ float As[32][132];
    __shared__ float Es[32][68];
    int tid = threadIdx.x;
    int tx = tid & 15, ty = tid >> 4;
    int n0 = blockIdx.x * 64, m0 = blockIdx.y * 128;
    float acc[8][4] = {};
    for (int kc = 0; kc < D_; kc += 32) {
        #pragma unroll
        for (int v = 0; v < 4; v++) {
            int q = tid + v*256;
            int am = q >> 3, ak = q & 7;
            float4 t4 = *(const float4*)(g_lhs_proj + (size_t)(m0+am)*D_ + kc + ak*4);
            As[ak*4+0][am] = t4.x; As[ak*4+1][am] = t4.y;
            As[ak*4+2][am] = t4.z; As[ak*4+3][am] = t4.w;
        }
        #pragma unroll
        for (int v = 0; v < 2; v++) {
            int q = tid + v*256;
            int en = q >> 3, ek = q & 7;
            int n = n0 + en;
            float4 t4 = make_float4(0.f,0.f,0.f,0.f);
            if (n < N_) t4 = *(const float4*)(E + (size_t)n*D_ + kc + ek*4);
            Es[ek*4+0][en] = t4.x; Es[ek*4+1][en] = t4.y;
            Es[ek*4+2][en] = t4.z; Es[ek*4+3][en] = t4.w;
        }
        __syncthreads();
        #pragma unroll
        for (int k = 0; k < 32; k++) {
            float4 a0 = *(const float4*)&As[k][ty*8];
            float4 a1 = *(const float4*)&As[k][ty*8+4];
            float4 w0 = *(const float4*)&Es[k][tx*4];
            float av[8] = {a0.x,a0.y,a0.z,a0.w,a1.x,a1.y,a1.z,a1.w};
            #pragma unroll
            for (int i = 0; i < 8; i++) {
                acc[i][0] = __fmaf_rn(av[i], w0.x, acc[i][0]);
                acc[i][1] = __fmaf_rn(av[i], w0.y, acc[i][1]);
                acc[i][2] = __fmaf_rn(av[i], w0.z, acc[i][2]);
                acc[i][3] = __fmaf_rn(av[i], w0.w, acc[i][3]);
            }
        }
        __syncthreads();
    }
    #pragma unroll
    for (int i = 0; i < 8; i++) {
        int m = m0 + ty*8 + i;
        float off = g_emb_off[m];
        #pragma unroll
        for (int j = 0; j < 4; j++) {
            int n = n0 + tx*4 + j;
            if (n < N_) out[(size_t)m*N_ + n] = __fadd_rn(acc[i][j], off);
        }
    }
}

// ------------------------- 4) scatter winners (FROZEN) -------------------------
__global__ void k_scatter(const int* __restrict__ bidx, const int* __restrict__ ridx,
                          float* __restrict__ out) {
    int i = blockIdx.x * blockDim.x + threadIdx.x;
    if (i >= NID_) return;
    size_t slot = (size_t)bidx[i]*N_ + ridx[i];
    if (g_pos[slot] == i) out[slot] = g_idgnn[i];
}

// ------------------------- 5) top-K: partial_sort emulation (FROZEN math) -------------------------
__device__ __forceinline__ unsigned fkey(float x) {
    unsigned u = __float_as_uint(x);
    return (u & 0x80000000u) ? ~u : (u | 0x80000000u);
}

__device__ void heap_adjust(int* hI, unsigned* hK, int hole, int len,
                            int vI, unsigned vK) {
    int top = hole;
    int sc = hole;
    while (sc < (len - 1) / 2) {
        sc = 2 * (sc + 1);
        if (hK[sc] > hK[sc - 1]) sc--;
        hI[hole] = hI[sc]; hK[hole] = hK[sc];
        hole = sc;
    }
    if ((len & 1) == 0 && sc == (len - 2) / 2) {
        sc = 2 * (sc + 1);
        hI[hole] = hI[sc - 1]; hK[hole] = hK[sc - 1];
        hole = sc - 1;
    }
    while (hole > top) {
        int par = (hole - 1) >> 1;
        if (hK[par] > vK) { hI[hole] = hI[par]; hK[hole] = hK[par]; hole = par; }
        else break;
    }
    hI[hole] = vI; hK[hole] = vK;
}

__global__ __launch_bounds__(128) void k_topk(const float* __restrict__ logits,
                                              float* __restrict__ out) {
    __shared__ int      sI[4][K_];
    __shared__ unsigned sK[4][K_];
    int w = threadIdx.x >> 5, lane = threadIdx.x & 31;
    int r = blockIdx.x * 4 + w;
    const float* row = logits + (size_t)r * N_;
    int* hI = sI[w]; unsigned* hK = sK[w];

    for (int i = lane; i < K_; i += 32) { hI[i] = i; hK[i] = fkey(row[i]); }
    __syncwarp();
    if (lane == 0)
        for (int p = (K_ - 2) / 2; p >= 0; p--)
            heap_adjust(hI, hK, p, K_, hI[p], hK[p]);
    __syncwarp();
    unsigned kmin = hK[0];

    // double-buffered 512-wide windows; processing order identical to sequential
    unsigned cur[16], nxt[16];
    #pragma unroll
    for (int j = 0; j < 16; j++) {
        int i = K_ + j*32 + lane;
        cur[j] = (i < N_) ? fkey(__ldg(row + i)) : 0u;
    }
    for (int base = K_; base < N_; base += 512) {
        int nb = base + 512;
        #pragma unroll
        for (int j = 0; j < 16; j++) {
            int i = nb + j*32 + lane;
            nxt[j] = (nb < N_ && i < N_) ? fkey(__ldg(row + i)) : 0u;
        }
        unsigned wm = cur[0];
        #pragma unroll
        for (int j = 1; j < 16; j++) wm = (cur[j] > wm) ? cur[j] : wm;
        if (__ballot_sync(0xffffffffu, wm > kmin) != 0u) {
            #pragma unroll
            for (int j = 0; j < 16; j++) {
                int ib = base + j*32;
                if (ib >= N_) break;
                unsigned m = __ballot_sync(0xffffffffu, (ib + lane) < N_ && cur[j] > kmin);
                while (m) {
                    int l = __ffs(m) - 1; m &= m - 1;
                    unsigned kv = __shfl_sync(0xffffffffu, cur[j], l);
                    if (lane == 0 && kv > kmin)
                        heap_adjust(hI, hK, 0, K_, ib + l, kv);
                    __syncwarp();
                    kmin = hK[0];
                }
            }
        }
        #pragma unroll
        for (int j = 0; j < 16; j++) cur[j] = nxt[j];
    }

    if (lane == 0)
        for (int len = K_; len > 1; len--) {
            int vI = hI[len-1]; unsigned vK = hK[len-1];
            hI[len-1] = hI[0]; hK[len-1] = hK[0];
            heap_adjust(hI, hK, 0, len - 1, vI, vK);
        }
    __syncwarp();
    for (int t = lane; t < K_; t += 32) {
        int idx = hI[t];
        g_topk[r*K_ + t] = idx;
        out[(size_t)B_*N_ + (size_t)B_*K_ + r*K_ + t] = (float)idx;
    }
}

// ------------------------- 6) build sequence [M, 2D] -------------------------
__global__ void k_build(const float* __restrict__ gnn, const float* __restrict__ E,
                        const int* __restrict__ bidx) {
    int m = blockIdx.x;
    int t = threadIdx.x;          // 256 threads
    int idx = g_topk[m];
    if (idx < 0 || idx >= N_) idx = 0;
    float val;
    if (t < 128) {
        int q = g_pos[idx];              // faithful non-globalized lookup
        if (q >= 0) val = gnn[(size_t)q*C_ + t];
        else        val = E[(size_t)idx*C_ + t];
    } else {
        int b = m / K_;
        val = g_lhs_proj[(size_t)bidx[b]*D_ + (t - 128)];
    }
    g_x[(size_t)m*C2_ + t] = val;
}

// ------------------------- 7) 128x128 tiled GEMM core -------------------------
__device__ __forceinline__ void gemm128_body(const float* __restrict__ X,
                                             const float* __restrict__ W,
                                             const float* __restrict__ bias,
                                             float* __restrict__ Y,
                                             int Nd, int relu,
                                             int n0, int m0) {
    __shared__ float Xs[32][132];
    __shared__ float Ws[32][132];
    int tid = threadIdx.x, tx = tid & 15, ty = tid >> 4;
    float acc[8][8] = {};
    for (int kc = 0; kc < C2_; kc += 32) {
        #pragma unroll
        for (int v = 0; v < 4; v++) {
            int q = tid + v*256;
            int am = q >> 3, ak = q & 7;
            float4 t4 = *(const float4*)(X + (size_t)(m0+am)*C2_ + kc + ak*4);
            Xs[ak*4+0][am] = t4.x; Xs[ak*4+1][am] = t4.y;
            Xs[ak*4+2][am] = t4.z; Xs[ak*4+3][am] = t4.w;
        }
        #pragma unroll
        for (int v = 0; v < 4; v++) {
            int q = tid + v*256;
            int wk = q >> 5, n4 = q & 31;
            *(float4*)&Ws[wk][n4*4] = *(const float4*)(W + (size_t)(kc+wk)*Nd + n0 + n4*4);
        }
        __syncthreads();
        #pragma unroll
        for (int k = 0; k < 32; k++) {
            float4 aL = *(const float4*)&Xs[k][ty*4];
            float4 aH = *(const float4*)&Xs[k][64 + ty*4];
            float4 wL = *(const float4*)&Ws[k][tx*4];
            float4 wH = *(const float4*)&Ws[k][64 + tx*4];
            float av[8] = {aL.x,aL.y,aL.z,aL.w,aH.x,aH.y,aH.z,aH.w};
            float wv[8] = {wL.x,wL.y,wL.z,wL.w,wH.x,wH.y,wH.z,wH.w};
            #pragma unroll
            for (int i = 0; i < 8; i++)
                #pragma unroll
                for (int j = 0; j < 8; j++)
                    acc[i][j] = __fmaf_rn(av[i], wv[j], acc[i][j]);
        }
        __syncthreads();
    }
    #pragma unroll
    for (int i = 0; i < 8; i++) {
        int m = m0 + ((i < 4) ? (ty*4 + i) : (64 + ty*4 + i - 4));
        int nL = n0 + tx*4, nH = n0 + 64 + tx*4;
        float4 yL, yH;
        yL.x = acc[i][0] + bias[nL+0]; yL.y = acc[i][1] + bias[nL+1];
        yL.z = acc[i][2] + bias[nL+2]; yL.w = acc[i][3] + bias[nL+3];
        yH.x = acc[i][4] + bias[nH+0]; yH.y = acc[i][5] + bias[nH+1];
        yH.z = acc[i][6] + bias[nH+2]; yH.w = acc[i][7] + bias[nH+3];
        if (relu) {
            yL.x = fmaxf(yL.x,0.f); yL.y = fmaxf(yL.y,0.f);
            yL.z = fmaxf(yL.z,0.f); yL.w = fmaxf(yL.w,0.f);
            yH.x = fmaxf(yH.x,0.f); yH.y = fmaxf(yH.y,0.f);
            yH.z = fmaxf(yH.z,0.f); yH.w = fmaxf(yH.w,0.f);
        }
        *(float4*)(Y + (size_t)m*Nd + nL) = yL;
        *(float4*)(Y + (size_t)m*Nd + nH) = yH;
    }
}

__global__ __launch_bounds__(256, 2) void k_gemm128(const float* __restrict__ X,
                                                    const float* __restrict__ W,
                                                    const float* __restrict__ bias,
                                                    float* __restrict__ Y,
                                                    int Nd, int relu) {
    gemm128_body(X, W, bias, Y, Nd, relu, blockIdx.x * 128, blockIdx.y * 128);
}

__global__ __launch_bounds__(256, 2) void k_gemm128_qkv(const float* __restrict__ X,
                                                        const float* __restrict__ W0,
                                                        const float* __restrict__ W1,
                                                        const float* __restrict__ W2,
                                                        const float* __restrict__ b0,
                                                        const float* __restrict__ b1,
                                                        const float* __restrict__ b2,
                                                        float* __restrict__ Y0,
                                                        float* __restrict__ Y1,
                                                        float* __restrict__ Y2) {
    const float* W = (blockIdx.z == 0) ? W0 : (blockIdx.z == 1) ? W1 : W2;
    const float* bias = (blockIdx.z == 0) ? b0 : (blockIdx.z == 1) ? b1 : b2;
    float* Y = (blockIdx.z == 0) ? Y0 : (blockIdx.z == 1) ? Y1 : Y2;
    gemm128_body(X, W, bias, Y, C2_, 0, blockIdx.x * 128, blockIdx.y * 128);
}

// ------------------------- 8a) attention QK + softmax -> g_att -------------------------
#define ATT1_SMEM ((K_*C2_ + 8*104) * 4)
__global__ __launch_bounds__(256) void k_attn1() {
    extern __shared__ float sm[];
    float* Ks = sm;                       // [100][256] pre-scaled
    float* sc = sm + K_*C2_;              // [8][104]
    int b = blockIdx.x, t = threadIdx.x, w = t >> 5, lane = t & 31;
    const float* qp = g_q + (size_t)b*K_*C2_;
    const float* kp = g_k + (size_t)b*K_*C2_;
    for (int idx = t; idx < K_*C2_; idx += 256)
        Ks[idx] = kp[idx] * 0.0625f;      // 1/sqrt(256)
    __syncthreads();
    float* scw = sc + w*104;
    for (int qi = w; qi < K_; qi += 8) {
        float4 q0 = *(const float4*)(qp + (size_t)qi*C2_ + lane*4);
        float4 q1 = *(const float4*)(qp + (size_t)qi*C2_ + 128 + lane*4);
        for (int j = 0; j < K_; j++) {
            float4 k0 = *(const float4*)&Ks[j*C2_ + lane*4];
            float4 k1 = *(const float4*)&Ks[j*C2_ + 128 + lane*4];
            float s = q0.x*k0.x + q0.y*k0.y + q0.z*k0.z + q0.w*k0.w
                    + q1.x*k1.x + q1.y*k1.y + q1.z*k1.z + q1.w*k1.w;
            #pragma unroll
            for (int o = 16; o; o >>= 1) s += __shfl_down_sync(0xffffffffu, s, o);
            if (lane == 0) scw[j] = s;
        }
        __syncwarp();
        float mx = -3.4e38f;
        for (int j = lane; j < K_; j += 32) mx = fmaxf(mx, scw[j]);
        #pragma unroll
        for (int o = 16; o; o >>= 1) mx = fmaxf(mx, __shfl_xor_sync(0xffffffffu, mx, o));
        float sum = 0.f;
        float e0 = 0.f, e1 = 0.f, e2 = 0.f, e3 = 0.f;
        if (lane < K_)       { e0 = expf(scw[lane]      - mx); sum += e0; }
        if (lane + 32 < K_)  { e1 = expf(scw[lane + 32] - mx); sum += e1; }
        if (lane + 64 < K_)  { e2 = expf(scw[lane + 64] - mx); sum += e2; }
        if (lane + 96 < K_)  { e3 = expf(scw[lane + 96] - mx); sum += e3; }
        #pragma unroll
        for (int o = 16; o; o >>= 1) sum += __shfl_xor_sync(0xffffffffu, sum, o);
        float inv = 1.f / sum;
        float* pr = g_att + ((size_t)b*K_ + qi)*104;
        if (lane < K_)      pr[lane]      = e0 * inv;
        if (lane + 32 < K_) pr[lane + 32] = e1 * inv;
        if (lane + 64 < K_) pr[lane + 64] = e2 * inv;
        if (lane + 96 < K_) pr[lane + 96] = e3 * inv;
        __syncwarp();
    }
}

// ------------------------- 8b) attention AV -------------------------
#define ATT2_SMEM ((K_*C2_ + 8*104) * 4)
__global__ __launch_bounds__(256) void k_attn2() {
    extern __shared__ float sm[];
    float* Vs = sm;                       // [100][256]
    float* sc = sm + K_*C2_;              // [8][104]
    int b = blockIdx.x, t = threadIdx.x, w = t >> 5, lane = t & 31;
    const float* vp = g_v + (size_t)b*K_*C2_;
    for (int idx = t; idx < K_*C2_; idx += 256)
        Vs[idx] = vp[idx];
    __syncthreads();
    float* scw = sc + w*104;
    for (int qi = w; qi < K_; qi += 8) {
        const float* pr = g_att + ((size_t)b*K_ + qi)*104;
        for (int j = lane; j < K_; j += 32) scw[j] = pr[j];
        __syncwarp();
        float a0x=0.f,a0y=0.f,a0z=0.f,a0w=0.f,a1x=0.f,a1y=0.f,a1z=0.f,a1w=0.f;
        for (int j = 0; j < K_; j++) {
            float p = scw[j];
            float4 v0 = *(const float4*)&Vs[j*C2_ + lane*4];
            float4 v1 = *(const float4*)&Vs[j*C2_ + 128 + lane*4];
            a0x += p*v0.x; a0y += p*v0.y; a0z += p*v0.z; a0w += p*v0.w;
            a1x += p*v1.x; a1y += p*v1.y; a1z += p*v1.z; a1w += p*v1.w;
        }
        float* op = g_o + ((size_t)b*K_ + qi)*C2_;
        *(float4*)(op + lane*4)       = make_float4(a0x, a0y, a0z, a0w);
        *(float4*)(op + 128 + lane*4) = make_float4(a1x, a1y, a1z, a1w);
        __syncwarp();
    }
}

// ------------------------- 9) LayerNorm -------------------------
__global__ void k_ln(const float* __restrict__ A, const float* __restrict__ R,
                     const float* __restrict__ g, const float* __restrict__ bb,
                     float* __restrict__ Y) {
    __shared__ float red[256];
    __shared__ float s_m, s_r;
    int m = blockIdx.x, t = threadIdx.x;
    float x = A[(size_t)m*C2_ + t] + R[(size_t)m*C2_ + t];
    red[t] = x; __syncthreads();
    for (int s = 128; s; s >>= 1) { if (t < s) red[t] += red[t+s]; __syncthreads(); }
    if (t == 0) s_m = red[0] * (1.f/256.f);
    __syncthreads();
    float d = x - s_m;
    red[t] = d*d; __syncthreads();
    for (int s = 128; s; s >>= 1) { if (t < s) red[t] += red[t+s]; __syncthreads(); }
    if (t == 0) s_r = rsqrtf(red[0] * (1.f/256.f) + 1e-5f);
    __syncthreads();
    Y[(size_t)m*C2_ + t] = d * s_r * g[t] + bb[t];
}

// ------------------------- 10) tr_logits = dot(x[:,128:], tr) -------------------------
__global__ void k_final(float* __restrict__ out) {
    int m = blockIdx.x*8 + (threadIdx.x >> 5);
    int lane = threadIdx.x & 31;
    float4 a = *(const float4*)&g_x[(size_t)m*C2_ + 128 + lane*4];
    float4 c = *(const float4*)&g_tr[(size_t)m*D_ + lane*4];
    float s = a.x*c.x + a.y*c.y + a.z*c.z + a.w*c.w;
    #pragma unroll
    for (int o = 16; o; o >>= 1) s += __shfl_down_sync(0xffffffffu, s, o);
    if (lane == 0) out[(size_t)B_*N_ + m] = s;
}

// ------------------------- launch -------------------------
extern "C" void kernel_launch(void* const* d_in, const int* in_sizes, int n_in,
                              void* d_out, int out_size) {
    const float* lhs   = (const float*)d_in[0];
    const float* gnn   = (const float*)d_in[1];
    const int*   ridx  = (const int*)  d_in[2];
    const int*   bidx  = (const int*)  d_in[3];
    const float* E     = (const float*)d_in[4];
    const float* wproj = (const float*)d_in[5];
    const float* bproj = (const float*)d_in[6];
    const float* whead = (const float*)d_in[7];
    const float* bhead = (const float*)d_in[8];
    const float* woe   = (const float*)d_in[9];
    const float* boe   = (const float*)d_in[10];
    const float* woi   = (const float*)d_in[11];
    const float* boi   = (const float*)d_in[12];
    const float* wq    = (const float*)d_in[13];
    const float* bq    = (const float*)d_in[14];
    const float* wk    = (const float*)d_in[15];
    const float* bk    = (const float*)d_in[16];
    const float* wv    = (const float*)d_in[17];
    const float* bv    = (const float*)d_in[18];
    const float* wo    = (const float*)d_in[19];
    const float* bo    = (const float*)d_in[20];
    const float* ln1g  = (const float*)d_in[21];
    const float* ln1b  = (const float*)d_in[22];
    const float* wf    = (const float*)d_in[23];
    const float* bf    = (const float*)d_in[24];
    const float* ln2g  = (const float*)d_in[25];
    const float* ln2b  = (const float*)d_in[26];
    const float* wtr   = (const float*)d_in[27];
    const float* btr   = (const float*)d_in[28];
    float* out = (float*)d_out;

    cudaFuncSetAttribute(k_attn1, cudaFuncAttributeMaxDynamicSharedMemorySize, ATT1_SMEM);
    cudaFuncSetAttribute(k_attn2, cudaFuncAttributeMaxDynamicSharedMemorySize, ATT2_SMEM);

    float *x, *q, *k, *v, *o, *op, *h, *f, *x2, *tr;
    int* posp;
    cudaGetSymbolAddress((void**)&x,  g_x);
    cudaGetSymbolAddress((void**)&q,  g_q);
    cudaGetSymbolAddress((void**)&k,  g_k);
    cudaGetSymbolAddress((void**)&v,  g_v);
    cudaGetSymbolAddress((void**)&o,  g_o);
    cudaGetSymbolAddress((void**)&op, g_op);
    cudaGetSymbolAddress((void**)&h,  g_h);
    cudaGetSymbolAddress((void**)&f,  g_f);
    cudaGetSymbolAddress((void**)&x2, g_x2);
    cudaGetSymbolAddress((void**)&tr, g_tr);
    cudaGetSymbolAddress((void**)&posp, g_pos);

    cudaMemsetAsync(posp, 0xFF, (size_t)B_*N_*sizeof(int), 0);   // all -1
    k_lhsproj<<<B_, 128>>>(lhs, wproj, bproj, woe, boe, woi, boi);
    k_idgnn<<<NID_/4, 128>>>(gnn, lhs, bidx, ridx, whead, bhead);
    k_embgnn<<<dim3((N_+63)/64, 2), 256>>>(E, out);
    k_scatter<<<NID_/256, 256>>>(bidx, ridx, out);
    k_topk<<<B_/4, 128>>>(out, out);
    k_build<<<M_, 256>>>(gnn, E, bidx);

    dim3 gq(2, M_/128, 3), g1(2, M_/128), gt(1, M_/128);
    k_gemm128_qkv<<<gq, 256>>>(x, wq, wk, wv, bq, bk, bv, q, k, v);
    k_attn1<<<B_, 256, ATT1_SMEM>>>();
    k_attn2<<<B_, 256, ATT2_SMEM>>>();
    k_gemm128<<<g1, 256>>>(o,  wo, bo, op, C2_, 0);
    k_ln<<<M_, 256>>>(x, op, ln1g, ln1b, h);
    k_gemm128<<<g1, 256>>>(h,  wf, bf, f,  C2_, 1);
    k_ln<<<M_, 256>>>(h, f, ln2g, ln2b, x2);
    k_gemm128<<<gt, 256>>>(x2, wtr, btr, tr, D_, 0);
    k_final<<<M_/8, 256>>>(out);
}